// round 12
// baseline (speedup 1.0000x reference)
#include <cuda_runtime.h>

#define BB 4
#define CC 256
#define HH 256
#define WW 256
#define HWSZ (HH * WW)
#define NPIX (BB * HWSZ)
#define FULLMASK 0xFFFFFFFFu

#define NBLK 444
#define NTHR 256
#define NTH_TOT (NBLK * NTHR)
// plane geometry: row stride 272 floats (68 float4), plane col = image col + 4
// plane rows: 0,1 zero | 2..257 = image rows 0..255 | 258..295 zero
#define SP 272
#define SP4 68
#define PROWS 296
#define PLSZ (PROWS * SP)
#define PLSZ4 (PROWS * SP4)
// phase-2 warp tasks: 16 hbands x 16 rows, 4 batches, 256 channels
#define HBANDS 16
#define HROWS 16
#define NTASK2 (HBANDS * 4 * 256)      // 16384

// fv: +-1 if correct (sign = class) else 0.  iv: +-1/(cnt+1e-5) if mse-masked else 0.
__device__ float4 g_fvp4[BB * PLSZ4];
__device__ float4 g_ivp4[BB * PLSZ4];
__device__ unsigned char g_info[NPIX];
__device__ double g_loss[2];
__device__ int g_nsel[2], g_cal[2];
__device__ int g_task;
__device__ int g_bar_count = 0;
__device__ volatile int g_bar_gen = 0;

__device__ __forceinline__ void gridsync() {
    __syncthreads();
    if (threadIdx.x == 0) {
        __threadfence();
        int gen = g_bar_gen;
        if (atomicAdd(&g_bar_count, 1) == NBLK - 1) {
            g_bar_count = 0;
            __threadfence();
            g_bar_gen = gen + 1;
        } else {
            while (g_bar_gen == gen) { __nanosleep(64); }
        }
        __threadfence();
    }
    __syncthreads();
}

// u += x*f^2, v += x*f (per element)
__device__ __forceinline__ void accum4(const float4 xv, const float4 fv,
                                       float4& u, float4& v) {
    float s;
    s = xv.x * fv.x; v.x += s; u.x = fmaf(s, fv.x, u.x);
    s = xv.y * fv.y; v.y += s; u.y = fmaf(s, fv.y, u.y);
    s = xv.z * fv.z; v.z += s; u.z = fmaf(s, fv.z, u.z);
    s = xv.w * fv.w; v.w += s; u.w = fmaf(s, fv.w, u.w);
}
__device__ __forceinline__ void decum4(const float4 xv, const float4 fv,
                                       float4& u, float4& v) {
    float s;
    s = xv.x * fv.x; v.x -= s; u.x = fmaf(-s, fv.x, u.x);
    s = xv.y * fv.y; v.y -= s; u.y = fmaf(-s, fv.y, u.y);
    s = xv.z * fv.z; v.z -= s; u.z = fmaf(-s, fv.z, u.z);
    s = xv.w * fv.w; v.w -= s; u.w = fmaf(-s, fv.w, u.w);
}

// 8 sliding 5-wide window sums via prefix differences
__device__ __forceinline__ void win8(float el0, float el1, const float4 A,
                                     const float4 B, float er0, float er1,
                                     float* W) {
    float pm1 = el0 + el1;
    float q0 = pm1 + A.x;
    float q1 = q0 + A.y;
    float q2 = q1 + A.z;
    float q3 = q2 + A.w;
    float q4 = q3 + B.x;
    float q5 = q4 + B.y;
    float q6 = q5 + B.z;
    float q7 = q6 + B.w;
    float q8 = q7 + er0;
    float q9 = q8 + er1;
    W[0] = q2;
    W[1] = q3 - el0;
    W[2] = q4 - pm1;
    W[3] = q5 - q0;
    W[4] = q6 - q1;
    W[5] = q7 - q2;
    W[6] = q8 - q3;
    W[7] = q9 - q4;
}

// loss term: class = sign(s); dd = cen + a*(cen - U/2) - s*V/2
__device__ __forceinline__ void epi(float s, float U, float V, float cen,
                                    float& a0, float& a1) {
    float a = fabsf(s);
    float t1 = fmaf(-0.5f, U, cen);
    float dd = fmaf(a, t1, cen);
    dd = fmaf(-0.5f * s, V, dd);
    float q = dd * dd;
    if (s > 0.f) a1 += q; else if (s < 0.f) a0 += q;
}

__global__ void __launch_bounds__(NTHR, 3) kernFused(
    const float* __restrict__ x, const float* __restrict__ clf,
    const int* __restrict__ gt, float* __restrict__ out) {
    __shared__ double sred[2][8];
    const int tid0 = blockIdx.x * NTHR + threadIdx.x;
    const int lane = threadIdx.x & 31;
    const int wid = threadIdx.x >> 5;
    const float4 z4 = make_float4(0.f, 0.f, 0.f, 0.f);

    // ===== Phase 1a: zero planes + per-pixel info + counter resets =========
    for (int i = tid0; i < BB * PLSZ4; i += NTH_TOT) {
        g_fvp4[i] = z4;
        g_ivp4[i] = z4;
    }
    for (int p = tid0; p < NPIX; p += NTH_TOT) {
        if (p == 0) {
            g_loss[0] = 0.0; g_loss[1] = 0.0;
            g_nsel[0] = 0; g_nsel[1] = 0;
            g_cal[0] = 0; g_cal[1] = 0;
            g_task = 0;
        }
        int b = p >> 16;
        int hw = p & (HWSZ - 1);
        int h = hw >> 8;
        int w = hw & (WW - 1);
        int g = gt[p];
        float c0 = clf[(size_t)(b * 2) * HWSZ + hw];
        float c1 = clf[(size_t)(b * 2 + 1) * HWSZ + hw];
        int pred = (c1 > c0) ? 1 : 0;          // argmax ties -> index 0
        int correct = (pred == g) ? 1 : 0;
        int edge = (g == -1) ? 1 : 0;
        if (h < HH - 5) edge |= (gt[p + 5 * WW] != g) ? 1 : 0;
        if (w < WW - 5) edge |= (gt[p + 5] != g) ? 1 : 0;
        g_info[p] = (unsigned char)((g & 1) | (correct << 1) | (edge << 2));
    }
    gridsync();

    // ===== Phase 1b: ring counts -> fv/iv planes + counters =================
    for (int p = tid0; p < NPIX; p += NTH_TOT) {
        int b = p >> 16;
        int hw = p & (HWSZ - 1);
        int h = hw >> 8;
        int w = hw & (WW - 1);
        unsigned info = g_info[p];
        int g = info & 1;
        int correct = (info >> 1) & 1;
        int edge = (info >> 2) & 1;
        int cntCorr = 0, cntCls = 0;
#pragma unroll
        for (int dh = -2; dh <= 2; dh++) {
#pragma unroll
            for (int dw = -2; dw <= 2; dw++) {
                if (dh == 0 && dw == 0) continue;
                int hh = h + dh, wp = w + dw;
                if ((unsigned)hh < HH && (unsigned)wp < WW) {
                    unsigned qi = g_info[p + dh * WW + dw];
                    int same = ((int)(qi & 1) == g) ? 1 : 0;
                    cntCls += same;
                    cntCorr += same & (int)((qi >> 1) & 1);
                }
            }
        }
        int mse = correct & edge & (cntCorr >= 1 ? 1 : 0);
        int cal = edge & (cntCls >= 1 ? 1 : 0);

        float fv = correct ? (g ? 1.0f : -1.0f) : 0.0f;
        float inv = 1.0f / ((float)cntCorr + 1e-5f);
        float ivs = mse ? (g ? inv : -inv) : 0.0f;

        int pofs = (h + 2) * SP + (w + 4);
        ((float*)g_fvp4)[(size_t)b * PLSZ + pofs] = fv;
        ((float*)g_ivp4)[(size_t)b * PLSZ + pofs] = ivs;

        unsigned bm;
        bm = __ballot_sync(FULLMASK, mse && g == 0);
        if (lane == 0 && bm) atomicAdd(&g_nsel[0], __popc(bm));
        bm = __ballot_sync(FULLMASK, mse && g == 1);
        if (lane == 0 && bm) atomicAdd(&g_nsel[1], __popc(bm));
        bm = __ballot_sync(FULLMASK, cal && g == 0);
        if (lane == 0 && bm) atomicAdd(&g_cal[0], __popc(bm));
        bm = __ballot_sync(FULLMASK, cal && g == 1);
        if (lane == 0 && bm) atomicAdd(&g_cal[1], __popc(bm));
    }
    gridsync();

    // ===== Phase 2: full-width span-8 separable box filter ==================
    // Warp-task = (hband, b, ch), 16 output rows x 256 cols. Lane owns image
    // cols 8*lane..8*lane+7 (two aligned float4s) -> one warp covers the whole
    // row; warp-edge halos ARE the image boundary (plane zero pad + selects).
    // u = 5-row col sums of x*f^2, v = of x*f (slide: add r+2, use, sub r-2,
    // departing products recomputed from L1-hot reloads). 8 shuffles/row.
    float acc0 = 0.f, acc1 = 0.f;

    for (;;) {
        int tw;
        if (lane == 0) tw = atomicAdd(&g_task, 1);
        tw = __shfl_sync(FULLMASK, tw, 0);
        if (tw >= NTASK2) break;
        const int hb = tw & (HBANDS - 1);
        const int b = (tw >> 4) & 3;
        const int ch = tw >> 6;
        const int h0 = hb * HROWS;

        const float* xp = x + ((size_t)(b * CC + ch) << 16) + (lane << 3);
        const float4* pf = g_fvp4 + (size_t)b * PLSZ4 + (lane << 1) + 1;
        const float4* pi = g_ivp4 + (size_t)b * PLSZ4 + (lane << 1) + 1;

        float4 uA = z4, uB = z4, vA = z4, vB = z4;
        // prologue: image rows h0-2..h0+1 = plane rows h0..h0+3
#pragma unroll
        for (int j = 0; j < 4; j++) {
            int rr = h0 - 2 + j;
            int rc = rr < 0 ? 0 : rr;
            const float* xr = xp + (rc << 8);
            float4 xa = __ldg((const float4*)xr);
            float4 xb = __ldg((const float4*)(xr + 4));
            float4 fa = __ldg(pf + (h0 + j) * SP4);
            float4 fb = __ldg(pf + (h0 + j) * SP4 + 1);
            accum4(xa, fa, uA, vA);
            accum4(xb, fb, uB, vB);
        }

#pragma unroll 1
        for (int r = h0; r < h0 + HROWS; r++) {
            int ri = r + 2 > 255 ? 255 : r + 2;
            int rd = r - 2 < 0 ? 0 : r - 2;
            // incoming row r+2
            const float* xri = xp + (ri << 8);
            float4 xiA = __ldg((const float4*)xri);
            float4 xiB = __ldg((const float4*)(xri + 4));
            const float4* pfi = pf + (r + 4) * SP4;
            float4 fiA = __ldg(pfi);
            float4 fiB = __ldg(pfi + 1);
            accum4(xiA, fiA, uA, vA);
            accum4(xiB, fiB, uB, vB);

            // halo via 8 shuffles; image-boundary halos zeroed
            float eul0 = __shfl_up_sync(FULLMASK, uB.z, 1);
            float eul1 = __shfl_up_sync(FULLMASK, uB.w, 1);
            float evl0 = __shfl_up_sync(FULLMASK, vB.z, 1);
            float evl1 = __shfl_up_sync(FULLMASK, vB.w, 1);
            float eur0 = __shfl_down_sync(FULLMASK, uA.x, 1);
            float eur1 = __shfl_down_sync(FULLMASK, uA.y, 1);
            float evr0 = __shfl_down_sync(FULLMASK, vA.x, 1);
            float evr1 = __shfl_down_sync(FULLMASK, vA.y, 1);
            if (lane == 0) { eul0 = 0.f; eul1 = 0.f; evl0 = 0.f; evl1 = 0.f; }
            if (lane == 31) { eur0 = 0.f; eur1 = 0.f; evr0 = 0.f; evr1 = 0.f; }

            float U[8], V[8];
            win8(eul0, eul1, uA, uB, eur0, eur1, U);
            win8(evl0, evl1, vA, vB, evr0, evr1, V);

            // departing row r-2 (recompute products; L1-hot reloads)
            const float* xrd = xp + (rd << 8);
            float4 xdA = __ldg((const float4*)xrd);
            float4 xdB = __ldg((const float4*)(xrd + 4));
            const float4* pfd = pf + r * SP4;
            float4 fdA = __ldg(pfd);
            float4 fdB = __ldg(pfd + 1);
            decum4(xdA, fdA, uA, vA);
            decum4(xdB, fdB, uB, vB);

            // epilogue: center row r
            const float* xrc = xp + (r << 8);
            float4 xcA = __ldg((const float4*)xrc);
            float4 xcB = __ldg((const float4*)(xrc + 4));
            const float4* pir = pi + (r + 2) * SP4;
            float4 ivA = __ldg(pir);
            float4 ivB = __ldg(pir + 1);
            epi(ivA.x, U[0], V[0], xcA.x, acc0, acc1);
            epi(ivA.y, U[1], V[1], xcA.y, acc0, acc1);
            epi(ivA.z, U[2], V[2], xcA.z, acc0, acc1);
            epi(ivA.w, U[3], V[3], xcA.w, acc0, acc1);
            epi(ivB.x, U[4], V[4], xcB.x, acc0, acc1);
            epi(ivB.y, U[5], V[5], xcB.y, acc0, acc1);
            epi(ivB.z, U[6], V[6], xcB.z, acc0, acc1);
            epi(ivB.w, U[7], V[7], xcB.w, acc0, acc1);
        }
    }

    // warp reduce + block reduce -> 2 double atomics per block
#pragma unroll
    for (int o = 16; o; o >>= 1) {
        acc0 += __shfl_xor_sync(FULLMASK, acc0, o);
        acc1 += __shfl_xor_sync(FULLMASK, acc1, o);
    }
    if (lane == 0) { sred[0][wid] = (double)acc0; sred[1][wid] = (double)acc1; }
    __syncthreads();
    if (threadIdx.x == 0) {
        double t0 = 0.0, t1 = 0.0;
#pragma unroll
        for (int i = 0; i < 8; i++) { t0 += sred[0][i]; t1 += sred[1][i]; }
        atomicAdd(&g_loss[0], t0);
        atomicAdd(&g_loss[1], t1);
    }
    gridsync();

    // ===== Phase 3: finalize ================================================
    if (blockIdx.x == 0 && threadIdx.x == 0) {
        double total = 0.0;
        int ncls = 0;
#pragma unroll
        for (int c = 0; c < 2; c++) {
            int ns = *(volatile int*)&g_nsel[c];
            int ca = *(volatile int*)&g_cal[c];
            double ls = *(volatile double*)&g_loss[c];
            bool valid = (ca >= 1) && (ns >= 1);
            double denom = (double)ns * 256.0;
            if (denom < 1.0) denom = 1.0;
            if (valid) { total += ls / denom; ncls++; }
        }
        out[0] = (ncls == 0) ? 0.0f : (float)(total / (double)ncls);
    }
}

extern "C" void kernel_launch(void* const* d_in, const int* in_sizes, int n_in,
                              void* d_out, int out_size) {
    const float* xfeat = (const float*)d_in[0];   // [4,256,256,256] f32
    const float* clf   = (const float*)d_in[1];   // [4,2,256,256]   f32
    const int*   gt    = (const int*)d_in[2];     // [4,256,256]     i32
    float* out = (float*)d_out;

    kernFused<<<NBLK, NTHR>>>(xfeat, clf, gt, out);
}